// round 3
// baseline (speedup 1.0000x reference)
#include <cuda_runtime.h>
#include <math.h>

// Chamfer loss, B=4, C=3, Np=Ng=8192. R3:
//  - packed f32x2 FMA (FFMA2) => 2 g-points per fma-pipe op
//  - 2048 work units (64 p-tiles x 8 g-splits x 4 batches) for wave balance
//  - software-pipelined gt staging (LDG for next stage issued before compute)
//  - both row-min and col-min flushed via int atomicMin on positive float bits
//    (clamped >= EPS first), sqrt applied only in finalize (monotone).

#define BATCH   4
#define NPT     8192
#define TPQ     128                 // predict points per block
#define TGQ     128                 // gt points per stage
#define GSPLIT  8                   // g-range splits => NPT/GSPLIT = 1024 per unit
#define NSTAGES ((NPT / GSPLIT) / TGQ)   // 8
#define NTH     256                 // 16 (g=tx) x 16 (p=ty)
#define EPSF    1e-12f
#define FLTMAXI 0x7f7fffff

typedef unsigned long long u64;

__device__ int g_colmin[BATCH * NPT];
__device__ int g_rowmin[BATCH * NPT];

__global__ void init_kernel() {
    int i = blockIdx.x * blockDim.x + threadIdx.x;
    if (i < BATCH * NPT) { g_colmin[i] = FLTMAXI; g_rowmin[i] = FLTMAXI; }
}

__device__ __forceinline__ u64 pk2(float lo, float hi) {
    u64 r; asm("mov.b64 %0,{%1,%2};" : "=l"(r) : "f"(lo), "f"(hi)); return r;
}
__device__ __forceinline__ void upk2(float& lo, float& hi, u64 v) {
    asm("mov.b64 {%0,%1},%2;" : "=f"(lo), "=f"(hi) : "l"(v));
}
__device__ __forceinline__ u64 ffma2(u64 a, u64 b, u64 c) {
    u64 d; asm("fma.rn.f32x2 %0,%1,%2,%3;" : "=l"(d) : "l"(a), "l"(b), "l"(c)); return d;
}
__device__ __forceinline__ u64 fadd2(u64 a, u64 b) {
    u64 d; asm("add.rn.f32x2 %0,%1,%2;" : "=l"(d) : "l"(a), "l"(b)); return d;
}

__global__ __launch_bounds__(NTH, 2)
void chamfer_main(const float* __restrict__ P, const float* __restrict__ G) {
    const int b     = blockIdx.z;
    const int pbase = blockIdx.x * TPQ;
    const int gbeg  = blockIdx.y * (NPT / GSPLIT);
    const float* Pb = P + (size_t)b * 3 * NPT;
    const float* Gb = G + (size_t)b * 3 * NPT;
    const int tid = threadIdx.x;
    const int tx  = tid & 15;        // g direction
    const int ty  = tid >> 4;        // p direction

    __shared__ float4 sp[TPQ];
    // gt chunk stored attribute-major so a float2 LDS.64 yields a packed pair
    __shared__ float sgx[TGQ], sgy[TGQ], sgz[TGQ], sg2[TGQ];
    __shared__ float cbuf[16][TGQ];

    // ---- prologue: p tile + prefetch stage 0 ----
    float rx = 0.f, ry = 0.f, rz = 0.f;              // prefetch regs (tid < TGQ active)
    if (tid < TGQ) {
        rx = Gb[gbeg + tid];
        ry = Gb[NPT + gbeg + tid];
        rz = Gb[2 * NPT + gbeg + tid];
    }
    for (int i = tid; i < TPQ; i += NTH) {
        float px = Pb[pbase + i];
        float py = Pb[NPT + pbase + i];
        float pz = Pb[2 * NPT + pbase + i];
        sp[i] = make_float4(-2.f * px, -2.f * py, -2.f * pz,
                            px * px + py * py + pz * pz);
    }
    if (tid < TGQ) {
        sgx[tid] = rx; sgy[tid] = ry; sgz[tid] = rz;
        sg2[tid] = rx * rx + ry * ry + rz * rz;
    }
    __syncthreads();

    // per-thread p registers: broadcast-packed coords, scalar |p|^2
    u64 pa2[8], pb2[8], pc2[8];
    float pp2[8], rowmin[8];
#pragma unroll
    for (int ii = 0; ii < 8; ii++) {
        float4 v = sp[ty * 8 + ii];
        pa2[ii] = pk2(v.x, v.x);
        pb2[ii] = pk2(v.y, v.y);
        pc2[ii] = pk2(v.z, v.z);
        pp2[ii] = v.w;
        rowmin[ii] = 3.4e38f;
    }

    for (int s = 0; s < NSTAGES; s++) {
        // prefetch next stage's gt points (latency hidden under compute)
        if (s + 1 < NSTAGES && tid < TGQ) {
            int g = gbeg + (s + 1) * TGQ + tid;
            rx = Gb[g]; ry = Gb[NPT + g]; rz = Gb[2 * NPT + g];
        }

        // load this thread's packed g pairs: pair jjp covers g = 2*(jjp*16+tx)+{0,1}
        u64 gx2[4], gy2[4], gz2[4], g22[4];
#pragma unroll
        for (int jjp = 0; jjp < 4; jjp++) {
            int idx = 2 * (jjp * 16 + tx);
            gx2[jjp] = *reinterpret_cast<const u64*>(&sgx[idx]);
            gy2[jjp] = *reinterpret_cast<const u64*>(&sgy[idx]);
            gz2[jjp] = *reinterpret_cast<const u64*>(&sgz[idx]);
            g22[jjp] = *reinterpret_cast<const u64*>(&sg2[idx]);
        }

        float colm[8];
#pragma unroll
        for (int j = 0; j < 8; j++) colm[j] = 3.4e38f;

#pragma unroll
        for (int ii = 0; ii < 8; ii++) {
            u64 p2b = pk2(pp2[ii], pp2[ii]);
#pragma unroll
            for (int jjp = 0; jjp < 4; jjp++) {
                u64 e = ffma2(pc2[ii], gz2[jjp], g22[jjp]);
                e = ffma2(pb2[ii], gy2[jjp], e);
                e = ffma2(pa2[ii], gx2[jjp], e);
                u64 d2 = fadd2(e, p2b);
                float d0, d1; upk2(d0, d1, d2);
                rowmin[ii] = fminf(rowmin[ii], fminf(d0, d1));
                colm[2 * jjp]     = fminf(colm[2 * jjp],     d0);
                colm[2 * jjp + 1] = fminf(colm[2 * jjp + 1], d1);
            }
        }

        // column reduce across the 16 ty threads sharing each g column
#pragma unroll
        for (int jjp = 0; jjp < 4; jjp++) {
            int g = 2 * (jjp * 16 + tx);
            cbuf[ty][g]     = colm[2 * jjp];
            cbuf[ty][g + 1] = colm[2 * jjp + 1];
        }
        __syncthreads();

        if (tid < TGQ) {
            float m = cbuf[0][tid];
#pragma unroll
            for (int t = 1; t < 16; t++) m = fminf(m, cbuf[t][tid]);
            m = fmaxf(m, EPSF);   // clamp (matches ref) + positive => int order valid
            atomicMin(&g_colmin[b * NPT + gbeg + s * TGQ + tid], __float_as_int(m));
        }

        // stage s+1 -> smem (prefetch regs have landed by now)
        if (s + 1 < NSTAGES && tid < TGQ) {
            sgx[tid] = rx; sgy[tid] = ry; sgz[tid] = rz;
            sg2[tid] = rx * rx + ry * ry + rz * rz;
        }
        __syncthreads();
    }

    // row-min reduce across tx: lanes differing in low 4 bits share ty and
    // partition g columns -> xor-shuffle over 1,2,4,8 completes the min.
#pragma unroll
    for (int ii = 0; ii < 8; ii++) {
        float m = rowmin[ii];
#pragma unroll
        for (int off = 1; off < 16; off <<= 1)
            m = fminf(m, __shfl_xor_sync(0xffffffffu, m, off));
        if (tx == 0) {
            m = fmaxf(m, EPSF);
            atomicMin(&g_rowmin[b * NPT + pbase + ty * 8 + ii], __float_as_int(m));
        }
    }
}

__global__ void finalize_kernel(float* out) {
    __shared__ float sred[256];
    const int tid = threadIdx.x;
    float s = 0.f;
    for (int i = tid; i < BATCH * NPT; i += 256) {
        s += sqrtf(__int_as_float(g_colmin[i]));   // already clamped >= EPS
        s += sqrtf(__int_as_float(g_rowmin[i]));
    }
    sred[tid] = s;
    __syncthreads();
    for (int st = 128; st > 0; st >>= 1) {
        if (tid < st) sred[tid] += sred[tid + st];
        __syncthreads();
    }
    if (tid == 0)
        out[0] = sred[0] / (float)(BATCH * 2 * NPT);   // denom = B*(Np+Ng)
}

extern "C" void kernel_launch(void* const* d_in, const int* in_sizes, int n_in,
                              void* d_out, int out_size) {
    const float* P = (const float*)d_in[0];
    const float* G = (const float*)d_in[1];

    init_kernel<<<(BATCH * NPT + 255) / 256, 256>>>();

    dim3 grid(NPT / TPQ, GSPLIT, BATCH);   // 64 x 8 x 4 = 2048 blocks
    chamfer_main<<<grid, NTH>>>(P, G);

    finalize_kernel<<<1, 256>>>((float*)d_out);
}